// round 8
// baseline (speedup 1.0000x reference)
#include <cuda_runtime.h>
#include <cstddef>

#define TT 4096
#define BB 256

// ---- scratch (static __device__, no allocation) ----
__device__ float2 g_pre[(size_t)TT * 3 * BB];      // [t][c][b], c=0:pre_r,1:pre_z,2:pre_n (r,z pre-halved, b_hh folded)
__device__ float2 g_E[(size_t)(TT + 1) * BB];      // emission probs softmax, +1 pad row for backward prefetch
__device__ float2 g_h[(size_t)BB * TT];            // GRU hidden, [b][t]
__device__ float2 g_va[(size_t)BB * TT];           // forward linear alpha (arbitrary scale), [b][t]
__device__ float2 g_vb[(size_t)BB * TT];           // backward linear beta  (arbitrary scale), [b][t]

__device__ __forceinline__ float tanha(float x) {
    float r; asm("tanh.approx.f32 %0, %1;" : "=f"(r) : "f"(x)); return r;
}
__device__ __forceinline__ float frcp(float x) {
    float r; asm("rcp.approx.f32 %0, %1;" : "=f"(r) : "f"(x)); return r;
}

// =====================================================================
// K1: parallel precompute of GRU input gates + emitter probabilities
// block = 256 threads = 256 batches at one t-group; grid = T/4 blocks
// =====================================================================
__global__ __launch_bounds__(256) void k1_pre(
    const float* __restrict__ x,
    const float* __restrict__ w_ih, const float* __restrict__ b_ih,
    const float* __restrict__ b_hh,
    const float* __restrict__ fc1w, const float* __restrict__ fc1b,
    const float* __restrict__ fc2w, const float* __restrict__ fc2b)
{
    __shared__ float sp[80];
    int tid = threadIdx.x;
    if (tid < 18)      sp[tid] = w_ih[tid];
    else if (tid < 24) sp[tid] = b_ih[tid - 18];
    else if (tid < 30) sp[tid] = b_hh[tid - 24];
    else if (tid < 54) sp[tid] = fc1w[tid - 30];
    else if (tid < 62) sp[tid] = fc1b[tid - 54];
    else if (tid < 78) sp[tid] = fc2w[tid - 62];
    else if (tid < 80) sp[tid] = fc2b[tid - 78];
    __syncthreads();

    int b  = tid;                 // lane-fast batch -> coalesced t-major stores
    int t0 = blockIdx.x * 4;

    // pad row for backward E prefetch (block 0 only)
    if (blockIdx.x == 0) g_E[(size_t)TT * BB + b] = make_float2(1.f, 1.f);

    // 4 timesteps x 3 floats = 48B contiguous, 16B aligned
    const float4* xp = (const float4*)(x + ((size_t)b * TT + t0) * 3);
    float4 xa = xp[0], xb = xp[1], xc = xp[2];
    float xs[4][3] = {{xa.x, xa.y, xa.z}, {xa.w, xb.x, xb.y},
                      {xb.z, xb.w, xc.x}, {xc.y, xc.z, xc.w}};

#pragma unroll
    for (int u = 0; u < 4; u++) {
        int t = t0 + u;
        float x0 = xs[u][0], x1 = xs[u][1], x2 = xs[u][2];

        float ig[6];
#pragma unroll
        for (int j = 0; j < 6; j++)
            ig[j] = fmaf(sp[j * 3 + 0], x0,
                    fmaf(sp[j * 3 + 1], x1,
                    fmaf(sp[j * 3 + 2], x2, sp[18 + j])));
        float2 pr = make_float2(0.5f * (ig[0] + sp[24]), 0.5f * (ig[1] + sp[25]));
        float2 pz = make_float2(0.5f * (ig[2] + sp[26]), 0.5f * (ig[3] + sp[27]));
        float2 pn = make_float2(ig[4], ig[5]);
        g_pre[(size_t)(t * 3 + 0) * BB + b] = pr;
        g_pre[(size_t)(t * 3 + 1) * BB + b] = pz;
        g_pre[(size_t)(t * 3 + 2) * BB + b] = pn;

        // emitter: tanh MLP (D=3 -> 8 -> 2), then softmax probs
        float l0 = sp[78], l1 = sp[79];
#pragma unroll
        for (int e = 0; e < 8; e++) {
            float hv = tanha(fmaf(sp[30 + e * 3], x0,
                             fmaf(sp[31 + e * 3], x1,
                             fmaf(sp[32 + e * 3], x2, sp[54 + e]))));
            l0 = fmaf(sp[62 + e], hv, l0);
            l1 = fmaf(sp[70 + e], hv, l1);
        }
        float ed  = __expf(l1 - l0);
        float inv = frcp(1.f + ed);
        g_E[(size_t)t * BB + b] = make_float2(inv, ed * inv);
    }
}

// =====================================================================
// K2: three concurrent serial scans. 24 blocks x 32 threads.
//   blocks 0-7  : GRU       (256 chains)
//   blocks 8-15 : HMM fwd   (256 chains, linear space, renorm/8)
//   blocks 16-23: HMM bwd
// =====================================================================
__global__ __launch_bounds__(32) void k2_scan(
    const float* __restrict__ w_hh, const float* __restrict__ b_hh,
    const float* __restrict__ log_pi, const float* __restrict__ log_A)
{
    int lane = threadIdx.x;
    int role = blockIdx.x >> 3;
    int b    = (blockIdx.x & 7) * 32 + lane;

    if (role == 0) {
        // ---------------- GRU ----------------
        float wr00 = 0.5f * __ldg(w_hh + 0), wr01 = 0.5f * __ldg(w_hh + 1);
        float wr10 = 0.5f * __ldg(w_hh + 2), wr11 = 0.5f * __ldg(w_hh + 3);
        float wz00 = 0.5f * __ldg(w_hh + 4), wz01 = 0.5f * __ldg(w_hh + 5);
        float wz10 = 0.5f * __ldg(w_hh + 6), wz11 = 0.5f * __ldg(w_hh + 7);
        float wn00 = __ldg(w_hh + 8),  wn01 = __ldg(w_hh + 9);
        float wn10 = __ldg(w_hh + 10), wn11 = __ldg(w_hh + 11);
        float bn0 = __ldg(b_hh + 4), bn1 = __ldg(b_hh + 5);

        float2 bR[2][8], bZ[2][8], bN[2][8];
#pragma unroll
        for (int u = 0; u < 8; u++) {
            bR[0][u] = g_pre[(size_t)(u * 3 + 0) * BB + b];
            bZ[0][u] = g_pre[(size_t)(u * 3 + 1) * BB + b];
            bN[0][u] = g_pre[(size_t)(u * 3 + 2) * BB + b];
        }
        float h0 = 0.f, h1 = 0.f;
        int cur = 0;
        float2* hout = g_h + (size_t)b * TT;
        for (int tg = 0; tg < TT; tg += 8) {
            int nxt = cur ^ 1;
            if (tg + 8 < TT) {
#pragma unroll
                for (int u = 0; u < 8; u++) {
                    int t = tg + 8 + u;
                    bR[nxt][u] = g_pre[(size_t)(t * 3 + 0) * BB + b];
                    bZ[nxt][u] = g_pre[(size_t)(t * 3 + 1) * BB + b];
                    bN[nxt][u] = g_pre[(size_t)(t * 3 + 2) * BB + b];
                }
            }
#pragma unroll
            for (int u = 0; u < 8; u++) {
                float2 pr = bR[cur][u], pz = bZ[cur][u], pn = bN[cur][u];
                float tr0 = tanha(fmaf(wr00, h0, fmaf(wr01, h1, pr.x)));
                float tr1 = tanha(fmaf(wr10, h0, fmaf(wr11, h1, pr.y)));
                float tz0 = tanha(fmaf(wz00, h0, fmaf(wz01, h1, pz.x)));
                float tz1 = tanha(fmaf(wz10, h0, fmaf(wz11, h1, pz.y)));
                float hn0 = fmaf(wn00, h0, fmaf(wn01, h1, bn0));
                float hn1 = fmaf(wn10, h0, fmaf(wn11, h1, bn1));
                float n0 = tanha(fmaf(tr0, 0.5f * hn0, fmaf(0.5f, hn0, pn.x)));
                float n1 = tanha(fmaf(tr1, 0.5f * hn1, fmaf(0.5f, hn1, pn.y)));
                float z0 = fmaf(0.5f, tz0, 0.5f), omz0 = fmaf(-0.5f, tz0, 0.5f);
                float z1 = fmaf(0.5f, tz1, 0.5f), omz1 = fmaf(-0.5f, tz1, 0.5f);
                float nh0 = fmaf(omz0, n0, z0 * h0);
                float nh1 = fmaf(omz1, n1, z1 * h1);
                h0 = nh0; h1 = nh1;
                hout[tg + u] = make_float2(h0, h1);
            }
            cur = nxt;
        }
    } else {
        // shared transition matrix (row-softmax of log_A)
        float e00 = __expf(__ldg(log_A + 0)), e01 = __expf(__ldg(log_A + 1));
        float e10 = __expf(__ldg(log_A + 2)), e11 = __expf(__ldg(log_A + 3));
        float r0 = frcp(e00 + e01), r1 = frcp(e10 + e11);
        float A00 = e00 * r0, A01 = e01 * r0;
        float A10 = e10 * r1, A11 = e11 * r1;

        if (role == 1) {
            // ---------------- forward ----------------
            float p0e = __expf(__ldg(log_pi + 0)), p1e = __expf(__ldg(log_pi + 1));
            float rp = frcp(p0e + p1e);
            float pi0 = p0e * rp, pi1 = p1e * rp;

            float2 eb[2][8];
#pragma unroll
            for (int u = 0; u < 8; u++) eb[0][u] = g_E[(size_t)u * BB + b];
            float v0 = 0.f, v1 = 0.f;
            int cur = 0;
            float2* vout = g_va + (size_t)b * TT;
            for (int tg = 0; tg < TT; tg += 8) {
                int nxt = cur ^ 1;
                if (tg + 8 < TT) {
#pragma unroll
                    for (int u = 0; u < 8; u++)
                        eb[nxt][u] = g_E[(size_t)(tg + 8 + u) * BB + b];
                }
                if (tg) { float iv = frcp(v0 + v1); v0 *= iv; v1 *= iv; }
#pragma unroll
                for (int u = 0; u < 8; u++) {
                    float2 E = eb[cur][u];
                    if (u == 0 && tg == 0) {
                        v0 = pi0 * E.x; v1 = pi1 * E.y;
                    } else {
                        float u0 = fmaf(A00, v0, A10 * v1);
                        float u1 = fmaf(A01, v0, A11 * v1);
                        v0 = E.x * u0; v1 = E.y * u1;
                    }
                    vout[tg + u] = make_float2(v0, v1);
                }
                cur = nxt;
            }
        } else {
            // ---------------- backward ----------------
            float2 eb[2][8];
#pragma unroll
            for (int u = 0; u < 8; u++) eb[0][u] = g_E[(size_t)(TT - u) * BB + b];
            float w0 = 1.f, w1 = 1.f;
            int cur = 0;
            float2* vout = g_vb + (size_t)b * TT;
            for (int g = 0; g < TT / 8; g++) {
                int nxt = cur ^ 1;
                if (g + 1 < TT / 8) {
#pragma unroll
                    for (int u = 0; u < 8; u++)
                        eb[nxt][u] = g_E[(size_t)(TT - 8 * (g + 1) - u) * BB + b];
                }
                if (g) { float iv = frcp(w0 + w1); w0 *= iv; w1 *= iv; }
#pragma unroll
                for (int u = 0; u < 8; u++) {
                    int t = TT - 1 - 8 * g - u;
                    float2 E = eb[cur][u];        // = E[t+1] (pad row for t=T-1)
                    if (u == 0 && g == 0) {
                        w0 = 1.f; w1 = 1.f;
                    } else {
                        float u0 = E.x * w0, u1 = E.y * w1;
                        float nw0 = fmaf(A00, u0, A01 * u1);
                        float nw1 = fmaf(A10, u0, A11 * u1);
                        w0 = nw0; w1 = nw1;
                    }
                    vout[t] = make_float2(w0, w1);
                }
                cur = nxt;
            }
        }
    }
}

// =====================================================================
// K3: parallel epilogue: gamma/log_gamma, gating softmax, V, pi_log
// =====================================================================
__global__ __launch_bounds__(256) void k3_final(
    const float* __restrict__ Q,
    const float* __restrict__ Wg, const float* __restrict__ by,
    float* __restrict__ out)
{
    __shared__ float sW[20];
    __shared__ float sb[4];
    int tid = threadIdx.x;
    if (tid < 20) sW[tid] = Wg[tid];
    if (tid < 4)  sb[tid] = by[tid];
    __syncthreads();

    size_t gid = (size_t)blockIdx.x * 256 + tid;   // = b*T + t (lanes t-fast)
    float2 a  = g_va[gid];
    float2 bt = g_vb[gid];
    float2 h  = g_h[gid];

    // gamma / log_gamma (all scan renorm scales cancel here)
    float p0 = a.x * bt.x, p1 = a.y * bt.y;
    float inv = frcp(p0 + p1);
    float gm0 = p0 * inv, gm1 = p1 * inv;
    float lg0 = __logf(gm0), lg1 = __logf(gm1);

    // per-state gating softmax over A=5
    float s0 = 0.f, s1 = 0.f;
    float E0[5], E1[5];
#pragma unroll
    for (int j = 0; j < 5; j++) {
        E0[j] = __expf(fmaf(h.x, sW[j],      h.y * sW[5 + j]));
        E1[j] = __expf(fmaf(h.x, sW[10 + j], h.y * sW[15 + j]));
        s0 += E0[j]; s1 += E1[j];
    }
    float c0 = gm0 * frcp(s0), c1 = gm1 * frcp(s1);

    const float2* qp = (const float2*)(Q + gid * 10);
    float V0 = fmaf(gm0, sb[0], gm1 * sb[2]);
    float V1 = fmaf(gm0, sb[1], gm1 * sb[3]);
    float gv[5];
#pragma unroll
    for (int j = 0; j < 5; j++) {
        float ga = fmaf(c0, E0[j], c1 * E1[j]);
        gv[j] = ga;
        float2 q = qp[j];
        V0 = fmaf(ga, q.x, V0);
        V1 = fmaf(ga, q.y, V1);
    }
    float mx = fmaxf(V0, V1), mn = fminf(V0, V1);
    float lse = mx + __logf(1.f + __expf(mn - mx));

    const size_t N = (size_t)BB * TT;
    ((float2*)out)[gid] = make_float2(V0 - lse, V1 - lse);   // pi_log [B,T,2]
    float* gout = out + N * 2 + gid * 5;                     // g      [B,T,5]
#pragma unroll
    for (int j = 0; j < 5; j++) gout[j] = gv[j];
    ((float2*)(out + N * 7))[gid] = make_float2(lg0, lg1);   // log_gamma [B,T,2]
}

// =====================================================================
extern "C" void kernel_launch(void* const* d_in, const int* in_sizes, int n_in,
                              void* d_out, int out_size) {
    const float* x      = (const float*)d_in[0];
    const float* Q_seq  = (const float*)d_in[1];
    const float* log_pi = (const float*)d_in[2];
    const float* log_A  = (const float*)d_in[3];
    const float* fc1_w  = (const float*)d_in[4];
    const float* fc1_b  = (const float*)d_in[5];
    const float* fc2_w  = (const float*)d_in[6];
    const float* fc2_b  = (const float*)d_in[7];
    const float* w_ih   = (const float*)d_in[8];
    const float* w_hh   = (const float*)d_in[9];
    const float* b_ih   = (const float*)d_in[10];
    const float* b_hh   = (const float*)d_in[11];
    const float* Wg     = (const float*)d_in[12];
    const float* by     = (const float*)d_in[13];
    float* out = (float*)d_out;

    k1_pre<<<TT / 4, 256>>>(x, w_ih, b_ih, b_hh, fc1_w, fc1_b, fc2_w, fc2_b);
    k2_scan<<<24, 32>>>(w_hh, b_hh, log_pi, log_A);
    k3_final<<<(BB * TT) / 256, 256>>>(Q_seq, Wg, by, out);
}

// round 9
// speedup vs baseline: 1.7477x; 1.7477x over previous
#include <cuda_runtime.h>
#include <cstddef>

#define TT 4096
#define BB 256

// ---- scratch (static __device__, no allocation) ----
__device__ float2 g_pre[(size_t)TT * 3 * BB];      // [t][c][b], c=0:pre_r,1:pre_z,2:pre_n (r,z pre-halved, b_hh folded)
__device__ float2 g_E[(size_t)(TT + 1) * BB];      // emission probs softmax, +1 pad row for backward prefetch
__device__ float2 g_h[(size_t)BB * TT];            // GRU hidden, [b][t]
__device__ float2 g_va[(size_t)BB * TT];           // forward linear alpha (arbitrary scale), [b][t]
__device__ float2 g_vb[(size_t)BB * TT];           // backward linear beta  (arbitrary scale), [b][t]

__device__ __forceinline__ float tanha(float x) {
    float r; asm("tanh.approx.f32 %0, %1;" : "=f"(r) : "f"(x)); return r;
}
__device__ __forceinline__ float frcp(float x) {
    float r; asm("rcp.approx.f32 %0, %1;" : "=f"(r) : "f"(x)); return r;
}

// =====================================================================
// K1: parallel precompute of GRU input gates + emitter probabilities
// =====================================================================
__global__ __launch_bounds__(256) void k1_pre(
    const float* __restrict__ x,
    const float* __restrict__ w_ih, const float* __restrict__ b_ih,
    const float* __restrict__ b_hh,
    const float* __restrict__ fc1w, const float* __restrict__ fc1b,
    const float* __restrict__ fc2w, const float* __restrict__ fc2b)
{
    __shared__ float sp[80];
    int tid = threadIdx.x;
    if (tid < 18)      sp[tid] = w_ih[tid];
    else if (tid < 24) sp[tid] = b_ih[tid - 18];
    else if (tid < 30) sp[tid] = b_hh[tid - 24];
    else if (tid < 54) sp[tid] = fc1w[tid - 30];
    else if (tid < 62) sp[tid] = fc1b[tid - 54];
    else if (tid < 78) sp[tid] = fc2w[tid - 62];
    else if (tid < 80) sp[tid] = fc2b[tid - 78];
    __syncthreads();

    int b  = tid;                 // lane-fast batch -> coalesced t-major stores
    int t0 = blockIdx.x * 4;

    // pad row for backward E prefetch (block 0 only)
    if (blockIdx.x == 0) g_E[(size_t)TT * BB + b] = make_float2(1.f, 1.f);

    // 4 timesteps x 3 floats = 48B contiguous, 16B aligned
    const float4* xp = (const float4*)(x + ((size_t)b * TT + t0) * 3);
    float4 xa = xp[0], xb = xp[1], xc = xp[2];
    float xs[4][3] = {{xa.x, xa.y, xa.z}, {xa.w, xb.x, xb.y},
                      {xb.z, xb.w, xc.x}, {xc.y, xc.z, xc.w}};

#pragma unroll
    for (int u = 0; u < 4; u++) {
        int t = t0 + u;
        float x0 = xs[u][0], x1 = xs[u][1], x2 = xs[u][2];

        float ig[6];
#pragma unroll
        for (int j = 0; j < 6; j++)
            ig[j] = fmaf(sp[j * 3 + 0], x0,
                    fmaf(sp[j * 3 + 1], x1,
                    fmaf(sp[j * 3 + 2], x2, sp[18 + j])));
        float2 pr = make_float2(0.5f * (ig[0] + sp[24]), 0.5f * (ig[1] + sp[25]));
        float2 pz = make_float2(0.5f * (ig[2] + sp[26]), 0.5f * (ig[3] + sp[27]));
        float2 pn = make_float2(ig[4], ig[5]);
        g_pre[(size_t)(t * 3 + 0) * BB + b] = pr;
        g_pre[(size_t)(t * 3 + 1) * BB + b] = pz;
        g_pre[(size_t)(t * 3 + 2) * BB + b] = pn;

        // emitter: tanh MLP (D=3 -> 8 -> 2), then softmax probs
        float l0 = sp[78], l1 = sp[79];
#pragma unroll
        for (int e = 0; e < 8; e++) {
            float hv = tanha(fmaf(sp[30 + e * 3], x0,
                             fmaf(sp[31 + e * 3], x1,
                             fmaf(sp[32 + e * 3], x2, sp[54 + e]))));
            l0 = fmaf(sp[62 + e], hv, l0);
            l1 = fmaf(sp[70 + e], hv, l1);
        }
        float ed  = __expf(l1 - l0);
        float inv = frcp(1.f + ed);
        g_E[(size_t)t * BB + b] = make_float2(inv, ed * inv);
    }
}

// =====================================================================
// K2 helpers: register-resident pipelined buffers (all indices are
// compile-time constants -> no local-memory spills)
// =====================================================================
struct GruW {
    float wr00, wr01, wr10, wr11;
    float wz00, wz01, wz10, wz11;
    float wn00, wn01, wn10, wn11;
    float bn0, bn1;
};

__device__ __forceinline__ void gru_load(float2 (&R)[8], float2 (&Z)[8],
                                         float2 (&N)[8], int tg, int b)
{
#pragma unroll
    for (int u = 0; u < 8; u++) {
        int t = tg + u;
        R[u] = g_pre[(size_t)(t * 3 + 0) * BB + b];
        Z[u] = g_pre[(size_t)(t * 3 + 1) * BB + b];
        N[u] = g_pre[(size_t)(t * 3 + 2) * BB + b];
    }
}

__device__ __forceinline__ void gru_body(const GruW& W,
                                         const float2 (&R)[8], const float2 (&Z)[8],
                                         const float2 (&N)[8],
                                         float& h0, float& h1,
                                         float2* __restrict__ hout, int tg)
{
#pragma unroll
    for (int u = 0; u < 8; u++) {
        float2 pr = R[u], pz = Z[u], pn = N[u];
        float tr0 = tanha(fmaf(W.wr00, h0, fmaf(W.wr01, h1, pr.x)));
        float tr1 = tanha(fmaf(W.wr10, h0, fmaf(W.wr11, h1, pr.y)));
        float tz0 = tanha(fmaf(W.wz00, h0, fmaf(W.wz01, h1, pz.x)));
        float tz1 = tanha(fmaf(W.wz10, h0, fmaf(W.wz11, h1, pz.y)));
        float hn0 = fmaf(W.wn00, h0, fmaf(W.wn01, h1, W.bn0));
        float hn1 = fmaf(W.wn10, h0, fmaf(W.wn11, h1, W.bn1));
        float n0 = tanha(fmaf(tr0, 0.5f * hn0, fmaf(0.5f, hn0, pn.x)));
        float n1 = tanha(fmaf(tr1, 0.5f * hn1, fmaf(0.5f, hn1, pn.y)));
        float z0 = fmaf(0.5f, tz0, 0.5f), omz0 = fmaf(-0.5f, tz0, 0.5f);
        float z1 = fmaf(0.5f, tz1, 0.5f), omz1 = fmaf(-0.5f, tz1, 0.5f);
        float nh0 = fmaf(omz0, n0, z0 * h0);
        float nh1 = fmaf(omz1, n1, z1 * h1);
        h0 = nh0; h1 = nh1;
        hout[tg + u] = make_float2(h0, h1);
    }
}

__device__ __forceinline__ void fwd_load(float2 (&E)[8], int tg, int b)
{
#pragma unroll
    for (int u = 0; u < 8; u++) E[u] = g_E[(size_t)(tg + u) * BB + b];
}

__device__ __forceinline__ void fwd_body(float A00, float A01, float A10, float A11,
                                         float pi0, float pi1,
                                         const float2 (&E)[8],
                                         float& v0, float& v1,
                                         float2* __restrict__ vout, int tg)
{
    if (tg) { float iv = frcp(v0 + v1); v0 *= iv; v1 *= iv; }
#pragma unroll
    for (int u = 0; u < 8; u++) {
        float2 e = E[u];
        if (u == 0 && tg == 0) {
            v0 = pi0 * e.x; v1 = pi1 * e.y;
        } else {
            float u0 = fmaf(A00, v0, A10 * v1);
            float u1 = fmaf(A01, v0, A11 * v1);
            v0 = e.x * u0; v1 = e.y * u1;
        }
        vout[tg + u] = make_float2(v0, v1);
    }
}

__device__ __forceinline__ void bwd_load(float2 (&E)[8], int g, int b)
{
#pragma unroll
    for (int u = 0; u < 8; u++) E[u] = g_E[(size_t)(TT - 8 * g - u) * BB + b];
}

__device__ __forceinline__ void bwd_body(float A00, float A01, float A10, float A11,
                                         const float2 (&E)[8],
                                         float& w0, float& w1,
                                         float2* __restrict__ vout, int g)
{
    if (g) { float iv = frcp(w0 + w1); w0 *= iv; w1 *= iv; }
#pragma unroll
    for (int u = 0; u < 8; u++) {
        int t = TT - 1 - 8 * g - u;
        float2 e = E[u];                  // = E[t+1] (pad row for t=T-1)
        if (u == 0 && g == 0) {
            w0 = 1.f; w1 = 1.f;
        } else {
            float u0 = e.x * w0, u1 = e.y * w1;
            float nw0 = fmaf(A00, u0, A01 * u1);
            float nw1 = fmaf(A10, u0, A11 * u1);
            w0 = nw0; w1 = nw1;
        }
        vout[t] = make_float2(w0, w1);
    }
}

// =====================================================================
// K2: three concurrent serial scans. 24 blocks x 32 threads.
//   blocks 0-7  : GRU       (256 chains)
//   blocks 8-15 : HMM fwd   (256 chains, linear space, renorm/8)
//   blocks 16-23: HMM bwd
// =====================================================================
__global__ __launch_bounds__(32) void k2_scan(
    const float* __restrict__ w_hh, const float* __restrict__ b_hh,
    const float* __restrict__ log_pi, const float* __restrict__ log_A)
{
    int lane = threadIdx.x;
    int role = blockIdx.x >> 3;
    int b    = (blockIdx.x & 7) * 32 + lane;

    if (role == 0) {
        // ---------------- GRU ----------------
        GruW W;
        W.wr00 = 0.5f * __ldg(w_hh + 0);  W.wr01 = 0.5f * __ldg(w_hh + 1);
        W.wr10 = 0.5f * __ldg(w_hh + 2);  W.wr11 = 0.5f * __ldg(w_hh + 3);
        W.wz00 = 0.5f * __ldg(w_hh + 4);  W.wz01 = 0.5f * __ldg(w_hh + 5);
        W.wz10 = 0.5f * __ldg(w_hh + 6);  W.wz11 = 0.5f * __ldg(w_hh + 7);
        W.wn00 = __ldg(w_hh + 8);   W.wn01 = __ldg(w_hh + 9);
        W.wn10 = __ldg(w_hh + 10);  W.wn11 = __ldg(w_hh + 11);
        W.bn0  = __ldg(b_hh + 4);   W.bn1  = __ldg(b_hh + 5);

        float2 Ra[8], Za[8], Na[8], Rb[8], Zb[8], Nb[8];
        float h0 = 0.f, h1 = 0.f;
        float2* hout = g_h + (size_t)b * TT;

        gru_load(Ra, Za, Na, 0, b);
        for (int tg = 0; tg < TT; tg += 16) {
            gru_load(Rb, Zb, Nb, tg + 8, b);
            gru_body(W, Ra, Za, Na, h0, h1, hout, tg);
            if (tg + 16 < TT) gru_load(Ra, Za, Na, tg + 16, b);
            gru_body(W, Rb, Zb, Nb, h0, h1, hout, tg + 8);
        }
    } else {
        // shared transition matrix (row-softmax of log_A)
        float e00 = __expf(__ldg(log_A + 0)), e01 = __expf(__ldg(log_A + 1));
        float e10 = __expf(__ldg(log_A + 2)), e11 = __expf(__ldg(log_A + 3));
        float r0 = frcp(e00 + e01), r1 = frcp(e10 + e11);
        float A00 = e00 * r0, A01 = e01 * r0;
        float A10 = e10 * r1, A11 = e11 * r1;

        if (role == 1) {
            // ---------------- forward ----------------
            float p0e = __expf(__ldg(log_pi + 0)), p1e = __expf(__ldg(log_pi + 1));
            float rp = frcp(p0e + p1e);
            float pi0 = p0e * rp, pi1 = p1e * rp;

            float2 Ea[8], Eb[8];
            float v0 = 0.f, v1 = 0.f;
            float2* vout = g_va + (size_t)b * TT;

            fwd_load(Ea, 0, b);
            for (int tg = 0; tg < TT; tg += 16) {
                fwd_load(Eb, tg + 8, b);
                fwd_body(A00, A01, A10, A11, pi0, pi1, Ea, v0, v1, vout, tg);
                if (tg + 16 < TT) fwd_load(Ea, tg + 16, b);
                fwd_body(A00, A01, A10, A11, pi0, pi1, Eb, v0, v1, vout, tg + 8);
            }
        } else {
            // ---------------- backward ----------------
            const int NG = TT / 8;        // 512 groups
            float2 Ea[8], Eb[8];
            float w0 = 1.f, w1 = 1.f;
            float2* vout = g_vb + (size_t)b * TT;

            bwd_load(Ea, 0, b);
            for (int g = 0; g < NG; g += 2) {
                bwd_load(Eb, g + 1, b);
                bwd_body(A00, A01, A10, A11, Ea, w0, w1, vout, g);
                if (g + 2 < NG) bwd_load(Ea, g + 2, b);
                bwd_body(A00, A01, A10, A11, Eb, w0, w1, vout, g + 1);
            }
        }
    }
}

// =====================================================================
// K3: parallel epilogue: gamma/log_gamma, gating softmax, V, pi_log
// =====================================================================
__global__ __launch_bounds__(256) void k3_final(
    const float* __restrict__ Q,
    const float* __restrict__ Wg, const float* __restrict__ by,
    float* __restrict__ out)
{
    __shared__ float sW[20];
    __shared__ float sb[4];
    int tid = threadIdx.x;
    if (tid < 20) sW[tid] = Wg[tid];
    if (tid < 4)  sb[tid] = by[tid];
    __syncthreads();

    size_t gid = (size_t)blockIdx.x * 256 + tid;   // = b*T + t (lanes t-fast)
    float2 a  = g_va[gid];
    float2 bt = g_vb[gid];
    float2 h  = g_h[gid];

    // gamma / log_gamma (all scan renorm scales cancel here)
    float p0 = a.x * bt.x, p1 = a.y * bt.y;
    float inv = frcp(p0 + p1);
    float gm0 = p0 * inv, gm1 = p1 * inv;
    float lg0 = __logf(gm0), lg1 = __logf(gm1);

    // per-state gating softmax over A=5
    float s0 = 0.f, s1 = 0.f;
    float E0[5], E1[5];
#pragma unroll
    for (int j = 0; j < 5; j++) {
        E0[j] = __expf(fmaf(h.x, sW[j],      h.y * sW[5 + j]));
        E1[j] = __expf(fmaf(h.x, sW[10 + j], h.y * sW[15 + j]));
        s0 += E0[j]; s1 += E1[j];
    }
    float c0 = gm0 * frcp(s0), c1 = gm1 * frcp(s1);

    const float2* qp = (const float2*)(Q + gid * 10);
    float V0 = fmaf(gm0, sb[0], gm1 * sb[2]);
    float V1 = fmaf(gm0, sb[1], gm1 * sb[3]);
    float gv[5];
#pragma unroll
    for (int j = 0; j < 5; j++) {
        float ga = fmaf(c0, E0[j], c1 * E1[j]);
        gv[j] = ga;
        float2 q = qp[j];
        V0 = fmaf(ga, q.x, V0);
        V1 = fmaf(ga, q.y, V1);
    }
    float mx = fmaxf(V0, V1), mn = fminf(V0, V1);
    float lse = mx + __logf(1.f + __expf(mn - mx));

    const size_t N = (size_t)BB * TT;
    ((float2*)out)[gid] = make_float2(V0 - lse, V1 - lse);   // pi_log [B,T,2]
    float* gout = out + N * 2 + gid * 5;                     // g      [B,T,5]
#pragma unroll
    for (int j = 0; j < 5; j++) gout[j] = gv[j];
    ((float2*)(out + N * 7))[gid] = make_float2(lg0, lg1);   // log_gamma [B,T,2]
}

// =====================================================================
extern "C" void kernel_launch(void* const* d_in, const int* in_sizes, int n_in,
                              void* d_out, int out_size) {
    const float* x      = (const float*)d_in[0];
    const float* Q_seq  = (const float*)d_in[1];
    const float* log_pi = (const float*)d_in[2];
    const float* log_A  = (const float*)d_in[3];
    const float* fc1_w  = (const float*)d_in[4];
    const float* fc1_b  = (const float*)d_in[5];
    const float* fc2_w  = (const float*)d_in[6];
    const float* fc2_b  = (const float*)d_in[7];
    const float* w_ih   = (const float*)d_in[8];
    const float* w_hh   = (const float*)d_in[9];
    const float* b_ih   = (const float*)d_in[10];
    const float* b_hh   = (const float*)d_in[11];
    const float* Wg     = (const float*)d_in[12];
    const float* by     = (const float*)d_in[13];
    float* out = (float*)d_out;

    k1_pre<<<TT / 4, 256>>>(x, w_ih, b_ih, b_hh, fc1_w, fc1_b, fc2_w, fc2_b);
    k2_scan<<<24, 32>>>(w_hh, b_hh, log_pi, log_A);
    k3_final<<<(BB * TT) / 256, 256>>>(Q_seq, Wg, by, out);
}